// round 16
// baseline (speedup 1.0000x reference)
#include <cuda_runtime.h>
#include <cstdint>

#define B_    32
#define HW_   128
#define NPIX  16384
#define NIMG  2048

// 128MB scratch, layout [b,c,h,w] throughout:
// after pass1': Fh(x); after podmix': Fw^-1-of-(f6+f2)-ish; pass3' finishes.
__device__ float g_scratch[(size_t)B_ * 64 * NPIX];
// pre-converted tf32 weights in per-thread fragment order
__device__ float g_wtf[8192];

// XOR-swizzled smem layout, stride 128 words (R5-proven)
__device__ __forceinline__ int sidx(int r, int h) {
    return r * 128 + ((((h >> 2) ^ r) & 31) << 2) + (h & 3);
}
__device__ __forceinline__ int sidx4(int r, int h4) {
    return r * 128 + (((h4 ^ r) & 31) << 2);
}

__device__ __forceinline__ uint32_t f2tf(float x) {
    uint32_t r; asm("cvt.rna.tf32.f32 %0, %1;" : "=r"(r) : "f"(x)); return r;
}
__device__ __forceinline__ float softth(float x, float t) {
    float tt = fmaxf(t, 0.f);
    return copysignf(fmaxf(fabsf(x) - tt, 0.f), x);
}
__device__ __forceinline__ void mma_tf32(float* d, uint32_t a0, uint32_t a1, uint32_t a2, uint32_t a3,
                                         uint32_t b0, uint32_t b1) {
    asm volatile(
        "mma.sync.aligned.m16n8k8.row.col.f32.tf32.tf32.f32 "
        "{%0,%1,%2,%3}, {%4,%5,%6,%7}, {%8,%9}, {%0,%1,%2,%3};\n"
        : "+f"(d[0]), "+f"(d[1]), "+f"(d[2]), "+f"(d[3])
        : "r"(a0), "r"(a1), "r"(a2), "r"(a3), "r"(b0), "r"(b1));
}
__device__ __forceinline__ void cpa16(uint32_t d, const void* s) {
    asm volatile("cp.async.cg.shared.global [%0], [%1], 16;" :: "r"(d), "l"(s));
}
__device__ __forceinline__ void cpa_commit_wait() {
    asm volatile("cp.async.commit_group;" ::: "memory");
    asm volatile("cp.async.wait_group 0;" ::: "memory");
}

// ---------------------------------------------------------------------------
// prep: conv_w -> tf32, fragment-ordered (unchanged, proven)
// ---------------------------------------------------------------------------
__global__ void prep_kernel(const float* __restrict__ W)
{
    int t = blockIdx.x * 256 + threadIdx.x;
    if (t >= 1024) return;
    int tig = t & 3, gid = (t >> 2) & 7, mq = (t >> 5) & 3, kb = t >> 7;
    int k0 = kb * 8 + tig;
    int r0 = mq * 16 + gid;
    float* o = g_wtf + t * 8;
    o[0] = __uint_as_float(f2tf(__ldg(W + r0 * 64 + k0)));
    o[1] = __uint_as_float(f2tf(__ldg(W + (r0 + 8) * 64 + k0)));
    o[2] = __uint_as_float(f2tf(__ldg(W + r0 * 64 + k0 + 4)));
    o[3] = __uint_as_float(f2tf(__ldg(W + (r0 + 8) * 64 + k0 + 4)));
    int r1 = r0 + 64;
    o[4] = __uint_as_float(f2tf(__ldg(W + r1 * 64 + k0)));
    o[5] = __uint_as_float(f2tf(__ldg(W + (r1 + 8) * 64 + k0)));
    o[6] = __uint_as_float(f2tf(__ldg(W + r1 * 64 + k0 + 4)));
    o[7] = __uint_as_float(f2tf(__ldg(W + (r1 + 8) * 64 + k0 + 4)));
}

// ---------------------------------------------------------------------------
// Pass 1 / Pass 3: FWHT along the h axis ONLY, layout [h][w] preserved.
// Structure = R5's validated phase-H (column transform) + R5 staging.
// ---------------------------------------------------------------------------
__global__ void __launch_bounds__(256, 2)
fwht_h_kernel(const float* __restrict__ in, float* __restrict__ out, float scale)
{
    extern __shared__ float s[];
    const int img = blockIdx.x;
    const int tid = threadIdx.x;
    const float* gin  = in  + (size_t)img * NPIX;
    float*       gout = out + (size_t)img * NPIX;

    // stage in: coalesced vec4 -> swizzled smem
    #pragma unroll
    for (int k = 0; k < 16; k++) {
        int gi = k * 256 + tid;
        int r  = gi >> 5;
        int c4 = gi & 31;
        float4 v4 = __ldg((const float4*)gin + gi);
        *(float4*)&s[sidx4(r, c4)] = v4;
    }
    __syncthreads();

    // column transform along h: thread (w = tid&127, hh = tid>>7)
    {
        int w = tid & 127, hh = tid >> 7;
        float reg[64];
        #pragma unroll
        for (int j = 0; j < 64; j++) {
            float a = s[sidx(j, w)];
            float b = s[sidx(j + 64, w)];
            reg[j] = hh ? (a - b) : (a + b);
        }
        #pragma unroll
        for (int st = 1; st < 64; st <<= 1)
            #pragma unroll
            for (int i = 0; i < 64; i++)
                if ((i & st) == 0) {
                    float a = reg[i], b = reg[i + st];
                    reg[i] = a + b;  reg[i + st] = a - b;
                }
        __syncthreads();   // all column reads done before overwrite
        #pragma unroll
        for (int j = 0; j < 64; j++)
            s[sidx(hh * 64 + j, w)] = reg[j];   // same orientation (no transpose)
    }
    __syncthreads();

    // stage out: rows vec4, scaled
    #pragma unroll
    for (int k = 0; k < 16; k++) {
        int gi = k * 256 + tid;
        int r  = gi >> 5;
        int c4 = gi & 31;
        float4 t = *(const float4*)&s[sidx4(r, c4)];
        ((float4*)gout)[gi] = make_float4(t.x*scale, t.y*scale, t.z*scale, t.w*scale);
    }
}

// ---------------------------------------------------------------------------
// Pass 2: per (b,h) tile [64 c][128 w]:
//   cp.async stage -> forward Fw per row (tf32-rounded) -> R15 GEMM
//   -> R15 epilogue -> inverse Fw per row -> store.
// Row transform: 4 threads/row (c = tid>>2, hf = (tid>>1)&1, sub = tid&1):
//   fold-64 at load, stages 1..16 in regs, stage-32 via shfl.xor(1). (R9-proven)
// ---------------------------------------------------------------------------
__global__ void __launch_bounds__(256, 2)
podmix_kernel(float* __restrict__ f2, const float* __restrict__ v,
              const float* __restrict__ T)
{
    __shared__ float sm[9216];
    float*    Bs  = sm;               // [64 c][136 w]
    uint32_t* Bsu = (uint32_t*)sm;
    float*    vs0 = sm + 8704;
    float*    Ts0 = vs0 + 128;
    float*    vs1 = Ts0 + 128;
    float*    Ts1 = vs1 + 128;

    const int b    = blockIdx.x >> 7;
    const int h    = blockIdx.x & 127;
    const int tid  = threadIdx.x;
    const int wid  = tid >> 5;
    const int lane = tid & 31;
    const int gid  = lane >> 2;   // 0..7
    const int tig  = lane & 3;    // 0..3
    const int mq   = wid & 3;     // o-quarter (16 rows)
    const int nh   = wid >> 2;    // w half

    // row transform identity
    const int rc  = tid >> 2;     // row c: 0..63
    const int hf  = (tid >> 1) & 1;
    const int sub = tid & 1;

    float* gtile = f2 + (size_t)(b * 64) * NPIX + h * 128;   // + c*NPIX + w

    // stage tile via cp.async (pure copy)
    {
        uint32_t bsd = (uint32_t)__cvta_generic_to_shared(Bs);
        #pragma unroll
        for (int k = 0; k < 8; k++) {
            int i4 = k * 256 + tid;          // 2048 float4
            int c  = i4 >> 5;
            int w4 = i4 & 31;
            cpa16(bsd + (c * 136 + w4 * 4) * 4,
                  (const float4*)(gtile + (size_t)c * NPIX) + w4);
        }
    }
    // v/T rows for this h (contiguous now)
    if (tid < 128) {
        vs0[tid] = __ldg(v + h * 128 + tid);
        Ts0[tid] = __ldg(T + h * 128 + tid);
    } else {
        int w = tid - 128;
        vs1[w] = __ldg(v + NPIX + h * 128 + w);
        Ts1[w] = __ldg(T + NPIX + h * 128 + w);
    }
    cpa_commit_wait();
    __syncthreads();

    // ---- forward Fw per row (write tf32-rounded) ----
    {
        float u[32];
        #pragma unroll
        for (int j4 = 0; j4 < 8; j4++) {
            float4 a = *(const float4*)&Bs[rc * 136 + sub * 32 + j4 * 4];
            float4 bb = *(const float4*)&Bs[rc * 136 + sub * 32 + 64 + j4 * 4];
            if (hf) {
                u[4*j4]   = a.x - bb.x; u[4*j4+1] = a.y - bb.y;
                u[4*j4+2] = a.z - bb.z; u[4*j4+3] = a.w - bb.w;
            } else {
                u[4*j4]   = a.x + bb.x; u[4*j4+1] = a.y + bb.y;
                u[4*j4+2] = a.z + bb.z; u[4*j4+3] = a.w + bb.w;
            }
        }
        #pragma unroll
        for (int st = 1; st < 32; st <<= 1)
            #pragma unroll
            for (int j = 0; j < 32; j++)
                if ((j & st) == 0) {
                    float a = u[j], bb = u[j + st];
                    u[j] = a + bb;  u[j + st] = a - bb;
                }
        #pragma unroll
        for (int j = 0; j < 32; j++) {
            float recv = __shfl_xor_sync(0xffffffffu, u[j], 1);
            u[j] = sub ? (recv - u[j]) : (u[j] + recv);
        }
        // shfl.sync converged the warp: all row reads complete. Write rounded.
        #pragma unroll
        for (int j4 = 0; j4 < 8; j4++) {
            uint4 q = make_uint4(f2tf(u[4*j4]), f2tf(u[4*j4+1]),
                                 f2tf(u[4*j4+2]), f2tf(u[4*j4+3]));
            *(uint4*)&Bsu[rc * 136 + hf * 64 + sub * 32 + j4 * 4] = q;
        }
    }
    __syncthreads();

    // ---- GEMM (R15-proven, unchanged) ----
    float acc[16][4];
    #pragma unroll
    for (int i = 0; i < 16; i++) {
        acc[i][0] = 0.f; acc[i][1] = 0.f; acc[i][2] = 0.f; acc[i][3] = 0.f;
    }
    const float4* Aw = (const float4*)g_wtf;
    #pragma unroll
    for (int kb = 0; kb < 8; kb++) {
        int ai = (((kb * 4 + mq) * 8 + gid) * 4 + tig) * 2;
        float4 lo = __ldg(Aw + ai);
        float4 hi = __ldg(Aw + ai + 1);
        uint32_t a0 = __float_as_uint(lo.x), a1 = __float_as_uint(lo.y);
        uint32_t a2 = __float_as_uint(lo.z), a3 = __float_as_uint(lo.w);
        uint32_t a4 = __float_as_uint(hi.x), a5 = __float_as_uint(hi.y);
        uint32_t a6 = __float_as_uint(hi.z), a7 = __float_as_uint(hi.w);
        int r0 = (kb * 8 + tig) * 136 + nh * 64 + gid;
        int r1 = r0 + 4 * 136;
        #pragma unroll
        for (int nb = 0; nb < 8; nb++) {
            uint32_t b0 = Bsu[r0 + nb * 8];
            uint32_t b1 = Bsu[r1 + nb * 8];
            mma_tf32(acc[nb],     a0, a1, a2, a3, b0, b1);   // pod 0
            mma_tf32(acc[8 + nb], a4, a5, a6, a7, b0, b1);   // pod 1
        }
    }
    __syncthreads();   // all GEMM reads of Bs done

    // ---- epilogue (R15-proven, unchanged): u = s0+s1+z into Bs ----
    {
        const int o = mq * 16 + gid;
        #pragma unroll
        for (int nb = 0; nb < 8; nb++) {
            int w = nh * 64 + nb * 8 + 2 * tig;
            float v0h = vs0[w], v0h1 = vs0[w+1], t0h = Ts0[w], t0h1 = Ts0[w+1];
            float v1h = vs1[w], v1h1 = vs1[w+1], t1h = Ts1[w], t1h1 = Ts1[w+1];
            float2 f0 = *(const float2*)&Bs[o * 136 + w];
            float2 f1 = *(const float2*)&Bs[(o + 8) * 136 + w];
            float2 r0 = make_float2(
                softth(v0h  * acc[nb][0], t0h)  + softth(v1h  * acc[8+nb][0], t1h)  + f0.x,
                softth(v0h1 * acc[nb][1], t0h1) + softth(v1h1 * acc[8+nb][1], t1h1) + f0.y);
            float2 r1 = make_float2(
                softth(v0h  * acc[nb][2], t0h)  + softth(v1h  * acc[8+nb][2], t1h)  + f1.x,
                softth(v0h1 * acc[nb][3], t0h1) + softth(v1h1 * acc[8+nb][3], t1h1) + f1.y);
            *(float2*)&Bs[o * 136 + w]       = r0;
            *(float2*)&Bs[(o + 8) * 136 + w] = r1;
        }
    }
    __syncthreads();

    // ---- inverse Fw per row (unscaled; 1/16384 applied in pass 3) ----
    {
        float u[32];
        #pragma unroll
        for (int j4 = 0; j4 < 8; j4++) {
            float4 a  = *(const float4*)&Bs[rc * 136 + sub * 32 + j4 * 4];
            float4 bb = *(const float4*)&Bs[rc * 136 + sub * 32 + 64 + j4 * 4];
            if (hf) {
                u[4*j4]   = a.x - bb.x; u[4*j4+1] = a.y - bb.y;
                u[4*j4+2] = a.z - bb.z; u[4*j4+3] = a.w - bb.w;
            } else {
                u[4*j4]   = a.x + bb.x; u[4*j4+1] = a.y + bb.y;
                u[4*j4+2] = a.z + bb.z; u[4*j4+3] = a.w + bb.w;
            }
        }
        #pragma unroll
        for (int st = 1; st < 32; st <<= 1)
            #pragma unroll
            for (int j = 0; j < 32; j++)
                if ((j & st) == 0) {
                    float a = u[j], bb = u[j + st];
                    u[j] = a + bb;  u[j + st] = a - bb;
                }
        #pragma unroll
        for (int j = 0; j < 32; j++) {
            float recv = __shfl_xor_sync(0xffffffffu, u[j], 1);
            u[j] = sub ? (recv - u[j]) : (u[j] + recv);
        }
        #pragma unroll
        for (int j4 = 0; j4 < 8; j4++)
            *(float4*)&Bs[rc * 136 + hf * 64 + sub * 32 + j4 * 4] =
                make_float4(u[4*j4], u[4*j4+1], u[4*j4+2], u[4*j4+3]);
    }
    __syncthreads();

    // coalesced store back in place
    #pragma unroll
    for (int k = 0; k < 8; k++) {
        int i4 = k * 256 + tid;
        int c  = i4 >> 5;
        int w4 = i4 & 31;
        float4 t = *(const float4*)&Bs[c * 136 + w4 * 4];
        *((float4*)(gtile + (size_t)c * NPIX) + w4) = t;
    }
}

extern "C" void kernel_launch(void* const* d_in, const int* in_sizes, int n_in,
                              void* d_out, int out_size)
{
    (void)in_sizes; (void)n_in; (void)out_size;
    const float* x = (const float*)d_in[0];
    const float* v = (const float*)d_in[1];
    const float* T = (const float*)d_in[2];
    const float* W = (const float*)d_in[3];
    float* out = (float*)d_out;

    float* scratch = nullptr;
    cudaGetSymbolAddress((void**)&scratch, g_scratch);

    const int smem1 = 128 * 128 * 4;   // 65536 B
    cudaFuncSetAttribute(fwht_h_kernel, cudaFuncAttributeMaxDynamicSharedMemorySize, smem1);

    prep_kernel<<<4, 256>>>(W);
    fwht_h_kernel<<<NIMG, 256, smem1>>>(x, scratch, 1.0f);           // Fh only
    podmix_kernel<<<B_ * 128, 256>>>(scratch, v, T);                 // Fw, pod, Fw^-1
    fwht_h_kernel<<<NIMG, 256, smem1>>>(scratch, out, 1.0f / 16384.0f); // Fh^-1 + scale
}

// round 17
// speedup vs baseline: 1.0094x; 1.0094x over previous
#include <cuda_runtime.h>
#include <cstdint>

#define B_    32
#define HW_   128
#define NPIX  16384
#define NIMG  2048

// 128MB scratch, layout [b,c,h,w] throughout
__device__ float g_scratch[(size_t)B_ * 64 * NPIX];
// pre-converted tf32 weights in per-thread fragment order
__device__ float g_wtf[8192];

// XOR-swizzled smem layout, stride 128 words (R5-proven)
__device__ __forceinline__ int sidx(int r, int h) {
    return r * 128 + ((((h >> 2) ^ r) & 31) << 2) + (h & 3);
}
__device__ __forceinline__ int sidx4(int r, int h4) {
    return r * 128 + (((h4 ^ r) & 31) << 2);
}

__device__ __forceinline__ uint32_t f2tf(float x) {
    uint32_t r; asm("cvt.rna.tf32.f32 %0, %1;" : "=r"(r) : "f"(x)); return r;
}
__device__ __forceinline__ float softth(float x, float t) {
    float tt = fmaxf(t, 0.f);
    return copysignf(fmaxf(fabsf(x) - tt, 0.f), x);
}
__device__ __forceinline__ void mma_tf32(float* d, uint32_t a0, uint32_t a1, uint32_t a2, uint32_t a3,
                                         uint32_t b0, uint32_t b1) {
    asm volatile(
        "mma.sync.aligned.m16n8k8.row.col.f32.tf32.tf32.f32 "
        "{%0,%1,%2,%3}, {%4,%5,%6,%7}, {%8,%9}, {%0,%1,%2,%3};\n"
        : "+f"(d[0]), "+f"(d[1]), "+f"(d[2]), "+f"(d[3])
        : "r"(a0), "r"(a1), "r"(a2), "r"(a3), "r"(b0), "r"(b1));
}
__device__ __forceinline__ void cpa16(uint32_t d, const void* s) {
    asm volatile("cp.async.cg.shared.global [%0], [%1], 16;" :: "r"(d), "l"(s));
}
__device__ __forceinline__ void cpa_commit_wait() {
    asm volatile("cp.async.commit_group;" ::: "memory");
    asm volatile("cp.async.wait_group 0;" ::: "memory");
}

// ---------------------------------------------------------------------------
// prep: conv_w -> tf32, fragment-ordered (unchanged, proven)
// ---------------------------------------------------------------------------
__global__ void prep_kernel(const float* __restrict__ W)
{
    int t = blockIdx.x * 256 + threadIdx.x;
    if (t >= 1024) return;
    int tig = t & 3, gid = (t >> 2) & 7, mq = (t >> 5) & 3, kb = t >> 7;
    int k0 = kb * 8 + tig;
    int r0 = mq * 16 + gid;
    float* o = g_wtf + t * 8;
    o[0] = __uint_as_float(f2tf(__ldg(W + r0 * 64 + k0)));
    o[1] = __uint_as_float(f2tf(__ldg(W + (r0 + 8) * 64 + k0)));
    o[2] = __uint_as_float(f2tf(__ldg(W + r0 * 64 + k0 + 4)));
    o[3] = __uint_as_float(f2tf(__ldg(W + (r0 + 8) * 64 + k0 + 4)));
    int r1 = r0 + 64;
    o[4] = __uint_as_float(f2tf(__ldg(W + r1 * 64 + k0)));
    o[5] = __uint_as_float(f2tf(__ldg(W + (r1 + 8) * 64 + k0)));
    o[6] = __uint_as_float(f2tf(__ldg(W + r1 * 64 + k0 + 4)));
    o[7] = __uint_as_float(f2tf(__ldg(W + (r1 + 8) * 64 + k0 + 4)));
}

// ---------------------------------------------------------------------------
// Pass 1 / Pass 3: FWHT along the h axis ONLY (R16-proven, 43.3us).
// ---------------------------------------------------------------------------
__global__ void __launch_bounds__(256, 2)
fwht_h_kernel(const float* __restrict__ in, float* __restrict__ out, float scale)
{
    extern __shared__ float s[];
    const int img = blockIdx.x;
    const int tid = threadIdx.x;
    const float* gin  = in  + (size_t)img * NPIX;
    float*       gout = out + (size_t)img * NPIX;

    #pragma unroll
    for (int k = 0; k < 16; k++) {
        int gi = k * 256 + tid;
        int r  = gi >> 5;
        int c4 = gi & 31;
        float4 v4 = __ldg((const float4*)gin + gi);
        *(float4*)&s[sidx4(r, c4)] = v4;
    }
    __syncthreads();

    {
        int w = tid & 127, hh = tid >> 7;
        float reg[64];
        #pragma unroll
        for (int j = 0; j < 64; j++) {
            float a = s[sidx(j, w)];
            float b = s[sidx(j + 64, w)];
            reg[j] = hh ? (a - b) : (a + b);
        }
        #pragma unroll
        for (int st = 1; st < 64; st <<= 1)
            #pragma unroll
            for (int i = 0; i < 64; i++)
                if ((i & st) == 0) {
                    float a = reg[i], b = reg[i + st];
                    reg[i] = a + b;  reg[i + st] = a - b;
                }
        __syncthreads();
        #pragma unroll
        for (int j = 0; j < 64; j++)
            s[sidx(hh * 64 + j, w)] = reg[j];
    }
    __syncthreads();

    #pragma unroll
    for (int k = 0; k < 16; k++) {
        int gi = k * 256 + tid;
        int r  = gi >> 5;
        int c4 = gi & 31;
        float4 t = *(const float4*)&s[sidx4(r, c4)];
        ((float4*)gout)[gi] = make_float4(t.x*scale, t.y*scale, t.z*scale, t.w*scale);
    }
}

// ---------------------------------------------------------------------------
// Pass 2: per (b,h) tile [64 c][128 w]:
//   cp.async stage -> forward Fw per row -> GEMM -> epilogue -> inverse Fw.
// Row transform, SHFL-FREE: thread (rc=tid>>2, hf=(tid>>1)&1, sub=tid&1)
// folds BOTH stage-64 and stage-32 at load:
//   u[j] = (x[j] +- x[j+64]) +-' (x[j+32] +- x[j+96]),  +- by hf, +-' by sub
// then stages 1..16 thread-local. All 4 threads/row read the same addresses
// (smem broadcast). Output at w = hf*64 + sub*32 + j.
// ---------------------------------------------------------------------------
__global__ void __launch_bounds__(256, 2)
podmix_kernel(float* __restrict__ f2, const float* __restrict__ v,
              const float* __restrict__ T)
{
    __shared__ float sm[9216];
    float*    Bs  = sm;               // [64 c][136 w]
    uint32_t* Bsu = (uint32_t*)sm;
    float*    vs0 = sm + 8704;
    float*    Ts0 = vs0 + 128;
    float*    vs1 = Ts0 + 128;
    float*    Ts1 = vs1 + 128;

    const int b    = blockIdx.x >> 7;
    const int h    = blockIdx.x & 127;
    const int tid  = threadIdx.x;
    const int wid  = tid >> 5;
    const int lane = tid & 31;
    const int gid  = lane >> 2;   // 0..7
    const int tig  = lane & 3;    // 0..3
    const int mq   = wid & 3;     // o-quarter (16 rows)
    const int nh   = wid >> 2;    // w half

    // row-transform identity
    const int rc  = tid >> 2;     // row c: 0..63
    const int hf  = (tid >> 1) & 1;
    const int sub = tid & 1;
    const int wbase = hf * 64 + sub * 32;

    float* gtile = f2 + (size_t)(b * 64) * NPIX + h * 128;   // + c*NPIX + w

    // stage tile via cp.async (pure copy)
    {
        uint32_t bsd = (uint32_t)__cvta_generic_to_shared(Bs);
        #pragma unroll
        for (int k = 0; k < 8; k++) {
            int i4 = k * 256 + tid;          // 2048 float4
            int c  = i4 >> 5;
            int w4 = i4 & 31;
            cpa16(bsd + (c * 136 + w4 * 4) * 4,
                  (const float4*)(gtile + (size_t)c * NPIX) + w4);
        }
    }
    // v/T rows for this h (contiguous)
    if (tid < 128) {
        vs0[tid] = __ldg(v + h * 128 + tid);
        Ts0[tid] = __ldg(T + h * 128 + tid);
    } else {
        int w = tid - 128;
        vs1[w] = __ldg(v + NPIX + h * 128 + w);
        Ts1[w] = __ldg(T + NPIX + h * 128 + w);
    }
    cpa_commit_wait();
    __syncthreads();

    // ---- forward Fw per row (shfl-free, write tf32-rounded) ----
    {
        float u[32];
        const float* row = &Bs[rc * 136];
        #pragma unroll
        for (int j4 = 0; j4 < 8; j4++) {
            float4 a = *(const float4*)(row + j4 * 4);
            float4 bb = *(const float4*)(row + 32 + j4 * 4);
            float4 c = *(const float4*)(row + 64 + j4 * 4);
            float4 d = *(const float4*)(row + 96 + j4 * 4);
            float p0 = hf ? (a.x - c.x) : (a.x + c.x);
            float p1 = hf ? (a.y - c.y) : (a.y + c.y);
            float p2 = hf ? (a.z - c.z) : (a.z + c.z);
            float p3 = hf ? (a.w - c.w) : (a.w + c.w);
            float q0 = hf ? (bb.x - d.x) : (bb.x + d.x);
            float q1 = hf ? (bb.y - d.y) : (bb.y + d.y);
            float q2 = hf ? (bb.z - d.z) : (bb.z + d.z);
            float q3 = hf ? (bb.w - d.w) : (bb.w + d.w);
            u[4*j4]   = sub ? (p0 - q0) : (p0 + q0);
            u[4*j4+1] = sub ? (p1 - q1) : (p1 + q1);
            u[4*j4+2] = sub ? (p2 - q2) : (p2 + q2);
            u[4*j4+3] = sub ? (p3 - q3) : (p3 + q3);
        }
        #pragma unroll
        for (int st = 1; st < 32; st <<= 1)
            #pragma unroll
            for (int j = 0; j < 32; j++)
                if ((j & st) == 0) {
                    float a = u[j], bb = u[j + st];
                    u[j] = a + bb;  u[j + st] = a - bb;
                }
        __syncthreads();   // all row reads complete before overwrite
        #pragma unroll
        for (int j4 = 0; j4 < 8; j4++) {
            uint4 q = make_uint4(f2tf(u[4*j4]), f2tf(u[4*j4+1]),
                                 f2tf(u[4*j4+2]), f2tf(u[4*j4+3]));
            *(uint4*)&Bsu[rc * 136 + wbase + j4 * 4] = q;
        }
    }
    __syncthreads();

    // ---- GEMM (R15-proven, unchanged) ----
    float acc[16][4];
    #pragma unroll
    for (int i = 0; i < 16; i++) {
        acc[i][0] = 0.f; acc[i][1] = 0.f; acc[i][2] = 0.f; acc[i][3] = 0.f;
    }
    const float4* Aw = (const float4*)g_wtf;
    #pragma unroll
    for (int kb = 0; kb < 8; kb++) {
        int ai = (((kb * 4 + mq) * 8 + gid) * 4 + tig) * 2;
        float4 lo = __ldg(Aw + ai);
        float4 hi = __ldg(Aw + ai + 1);
        uint32_t a0 = __float_as_uint(lo.x), a1 = __float_as_uint(lo.y);
        uint32_t a2 = __float_as_uint(lo.z), a3 = __float_as_uint(lo.w);
        uint32_t a4 = __float_as_uint(hi.x), a5 = __float_as_uint(hi.y);
        uint32_t a6 = __float_as_uint(hi.z), a7 = __float_as_uint(hi.w);
        int r0 = (kb * 8 + tig) * 136 + nh * 64 + gid;
        int r1 = r0 + 4 * 136;
        #pragma unroll
        for (int nb = 0; nb < 8; nb++) {
            uint32_t b0 = Bsu[r0 + nb * 8];
            uint32_t b1 = Bsu[r1 + nb * 8];
            mma_tf32(acc[nb],     a0, a1, a2, a3, b0, b1);   // pod 0
            mma_tf32(acc[8 + nb], a4, a5, a6, a7, b0, b1);   // pod 1
        }
    }
    __syncthreads();   // all GEMM reads of Bs done

    // ---- epilogue (R15-proven, unchanged) ----
    {
        const int o = mq * 16 + gid;
        #pragma unroll
        for (int nb = 0; nb < 8; nb++) {
            int w = nh * 64 + nb * 8 + 2 * tig;
            float v0h = vs0[w], v0h1 = vs0[w+1], t0h = Ts0[w], t0h1 = Ts0[w+1];
            float v1h = vs1[w], v1h1 = vs1[w+1], t1h = Ts1[w], t1h1 = Ts1[w+1];
            float2 f0 = *(const float2*)&Bs[o * 136 + w];
            float2 f1 = *(const float2*)&Bs[(o + 8) * 136 + w];
            float2 r0 = make_float2(
                softth(v0h  * acc[nb][0], t0h)  + softth(v1h  * acc[8+nb][0], t1h)  + f0.x,
                softth(v0h1 * acc[nb][1], t0h1) + softth(v1h1 * acc[8+nb][1], t1h1) + f0.y);
            float2 r1 = make_float2(
                softth(v0h  * acc[nb][2], t0h)  + softth(v1h  * acc[8+nb][2], t1h)  + f1.x,
                softth(v0h1 * acc[nb][3], t0h1) + softth(v1h1 * acc[8+nb][3], t1h1) + f1.y);
            *(float2*)&Bs[o * 136 + w]       = r0;
            *(float2*)&Bs[(o + 8) * 136 + w] = r1;
        }
    }
    __syncthreads();

    // ---- inverse Fw per row (shfl-free; 1/16384 applied in pass 3) ----
    {
        float u[32];
        const float* row = &Bs[rc * 136];
        #pragma unroll
        for (int j4 = 0; j4 < 8; j4++) {
            float4 a = *(const float4*)(row + j4 * 4);
            float4 bb = *(const float4*)(row + 32 + j4 * 4);
            float4 c = *(const float4*)(row + 64 + j4 * 4);
            float4 d = *(const float4*)(row + 96 + j4 * 4);
            float p0 = hf ? (a.x - c.x) : (a.x + c.x);
            float p1 = hf ? (a.y - c.y) : (a.y + c.y);
            float p2 = hf ? (a.z - c.z) : (a.z + c.z);
            float p3 = hf ? (a.w - c.w) : (a.w + c.w);
            float q0 = hf ? (bb.x - d.x) : (bb.x + d.x);
            float q1 = hf ? (bb.y - d.y) : (bb.y + d.y);
            float q2 = hf ? (bb.z - d.z) : (bb.z + d.z);
            float q3 = hf ? (bb.w - d.w) : (bb.w + d.w);
            u[4*j4]   = sub ? (p0 - q0) : (p0 + q0);
            u[4*j4+1] = sub ? (p1 - q1) : (p1 + q1);
            u[4*j4+2] = sub ? (p2 - q2) : (p2 + q2);
            u[4*j4+3] = sub ? (p3 - q3) : (p3 + q3);
        }
        #pragma unroll
        for (int st = 1; st < 32; st <<= 1)
            #pragma unroll
            for (int j = 0; j < 32; j++)
                if ((j & st) == 0) {
                    float a = u[j], bb = u[j + st];
                    u[j] = a + bb;  u[j + st] = a - bb;
                }
        __syncthreads();
        #pragma unroll
        for (int j4 = 0; j4 < 8; j4++)
            *(float4*)&Bs[rc * 136 + wbase + j4 * 4] =
                make_float4(u[4*j4], u[4*j4+1], u[4*j4+2], u[4*j4+3]);
    }
    __syncthreads();

    // coalesced store back in place
    #pragma unroll
    for (int k = 0; k < 8; k++) {
        int i4 = k * 256 + tid;
        int c  = i4 >> 5;
        int w4 = i4 & 31;
        float4 t = *(const float4*)&Bs[c * 136 + w4 * 4];
        *((float4*)(gtile + (size_t)c * NPIX) + w4) = t;
    }
}

extern "C" void kernel_launch(void* const* d_in, const int* in_sizes, int n_in,
                              void* d_out, int out_size)
{
    (void)in_sizes; (void)n_in; (void)out_size;
    const float* x = (const float*)d_in[0];
    const float* v = (const float*)d_in[1];
    const float* T = (const float*)d_in[2];
    const float* W = (const float*)d_in[3];
    float* out = (float*)d_out;

    float* scratch = nullptr;
    cudaGetSymbolAddress((void**)&scratch, g_scratch);

    const int smem1 = 128 * 128 * 4;   // 65536 B
    cudaFuncSetAttribute(fwht_h_kernel, cudaFuncAttributeMaxDynamicSharedMemorySize, smem1);

    prep_kernel<<<4, 256>>>(W);
    fwht_h_kernel<<<NIMG, 256, smem1>>>(x, scratch, 1.0f);              // Fh
    podmix_kernel<<<B_ * 128, 256>>>(scratch, v, T);                    // Fw, pod, Fw^-1
    fwht_h_kernel<<<NIMG, 256, smem1>>>(scratch, out, 1.0f / 16384.0f); // Fh^-1 + scale
}